// round 1
// baseline (speedup 1.0000x reference)
#include <cuda_runtime.h>
#include <cuda_bf16.h>
#include <math.h>

#define NMAX 100000
#define EMAX 1600000

// Scratch (allocation-free rule: __device__ globals)
__device__ float g_support[(size_t)NMAX * 128];
__device__ float g_t[(size_t)NMAX * 128];
__device__ float g_sum[4][128];
__device__ float g_sq[4][128];
__device__ int   g_rowptr[NMAX + 1];

// ---------------------------------------------------------------------------
// Zero the BN stat accumulators (all 4 layers) once per launch.
__global__ void zero_stats_kernel() {
    int i = threadIdx.x;
    if (i < 128) {
        #pragma unroll
        for (int l = 0; l < 4; l++) { g_sum[l][i] = 0.f; g_sq[l][i] = 0.f; }
    }
}

// ---------------------------------------------------------------------------
// CSR row_ptr from sorted adj_row via binary search (lower_bound of r).
__global__ void rowptr_kernel(const int* __restrict__ adj_row, int N, int E) {
    int r = blockIdx.x * blockDim.x + threadIdx.x;
    if (r > N) return;
    int lo = 0, hi = E;
    while (lo < hi) {
        int mid = (lo + hi) >> 1;
        if (adj_row[mid] < r) lo = mid + 1; else hi = mid;
    }
    g_rowptr[r] = lo;
}

// ---------------------------------------------------------------------------
// Tiled fp32 SGEMM: C[N,OUT] = A[N,K] @ W[K,OUT]
// BM=64 rows/block, BK=32, 16x16 threads, each thread: 4 x (OUT/16) outputs.
template<int K, int OUT>
__global__ void gemm_kernel(const float* __restrict__ A, const float* __restrict__ W,
                            float* __restrict__ C, int N) {
    constexpr int BM = 64, BK = 32;
    constexpr int TM = 4;
    constexpr int TN = OUT / 16;           // 8, 8, 4, 2
    __shared__ float As[BK][BM];           // A tile, transposed
    __shared__ float Ws[BK][OUT];

    const int tx = threadIdx.x;            // 0..15 -> col groups
    const int ty = threadIdx.y;            // 0..15 -> row groups
    const int tid = ty * 16 + tx;
    const int row0 = blockIdx.x * BM;

    float acc[TM][TN];
    #pragma unroll
    for (int i = 0; i < TM; i++)
        #pragma unroll
        for (int j = 0; j < TN; j++) acc[i][j] = 0.f;

    for (int kb = 0; kb < K; kb += BK) {
        // Load A tile (transposed): 64x32 elems, coalesced over k
        #pragma unroll
        for (int p = 0; p < (BM * BK) / 256; p++) {
            int idx = p * 256 + tid;
            int r = idx / BK, k = idx % BK;
            int gr = row0 + r;
            float v = (gr < N) ? A[(size_t)gr * K + kb + k] : 0.f;
            As[k][r] = v;
        }
        // Load W tile: BKxOUT elems, coalesced over c
        #pragma unroll
        for (int p = 0; p < (BK * OUT) / 256; p++) {
            int idx = p * 256 + tid;
            int k = idx / OUT, c = idx % OUT;
            Ws[k][c] = W[(size_t)(kb + k) * OUT + c];
        }
        __syncthreads();

        #pragma unroll
        for (int k = 0; k < BK; k++) {
            float a[TM], w[TN];
            #pragma unroll
            for (int i = 0; i < TM; i++) a[i] = As[k][ty * TM + i];
            #pragma unroll
            for (int j = 0; j < TN; j++) w[j] = Ws[k][tx * TN + j];
            #pragma unroll
            for (int i = 0; i < TM; i++)
                #pragma unroll
                for (int j = 0; j < TN; j++)
                    acc[i][j] = fmaf(a[i], w[j], acc[i][j]);
        }
        __syncthreads();
    }

    #pragma unroll
    for (int i = 0; i < TM; i++) {
        int gr = row0 + ty * TM + i;
        if (gr < N) {
            float* crow = C + (size_t)gr * OUT + tx * TN;
            #pragma unroll
            for (int j = 0; j < TN; j++) crow[j] = acc[i][j];
        }
    }
}

// ---------------------------------------------------------------------------
// SpMM (warp per row, sorted rows / CSR ranges) + leaky_relu + elu fused,
// plus block-local BN stat accumulation (sum, sumsq per column).
template<int OUT, int LAYER>
__global__ void spmm_kernel(const float* __restrict__ support,
                            const int* __restrict__ col,
                            const float* __restrict__ vals,
                            float* __restrict__ t, int N) {
    constexpr int J = OUT / 32;
    __shared__ float ssum[OUT], ssq[OUT];
    const int tid = threadIdx.x;
    for (int i = tid; i < OUT; i += blockDim.x) { ssum[i] = 0.f; ssq[i] = 0.f; }
    __syncthreads();

    const int lane = tid & 31;
    const int warp = tid >> 5;
    const int row = blockIdx.x * 8 + warp;

    if (row < N) {
        float acc[J];
        #pragma unroll
        for (int j = 0; j < J; j++) acc[j] = 0.f;

        const int s = g_rowptr[row];
        const int e = g_rowptr[row + 1];
        for (int i = s; i < e; i++) {
            int c = __ldg(&col[i]);
            float v = __ldg(&vals[i]);
            const float* sp = support + (size_t)c * OUT;
            #pragma unroll
            for (int j = 0; j < J; j++)
                acc[j] = fmaf(v, __ldg(&sp[lane + 32 * j]), acc[j]);
        }
        float* trow = t + (size_t)row * OUT;
        #pragma unroll
        for (int j = 0; j < J; j++) {
            float a = acc[j];
            // leaky_relu(0.2) then elu: sign preserved -> single branch
            float tv = (a > 0.f) ? a : expm1f(0.2f * a);
            trow[lane + 32 * j] = tv;
            atomicAdd(&ssum[lane + 32 * j], tv);
            atomicAdd(&ssq[lane + 32 * j], tv * tv);
        }
    }
    __syncthreads();
    for (int i = tid; i < OUT; i += blockDim.x) {
        atomicAdd(&g_sum[LAYER][i], ssum[i]);
        atomicAdd(&g_sq[LAYER][i], ssq[i]);
    }
}

// ---------------------------------------------------------------------------
// BatchNorm (affine=False, biased var): out = (t - mean) * rsqrt(var + eps)
template<int OUT, int LAYER>
__global__ void norm_kernel(const float* __restrict__ t, float* __restrict__ out, int N) {
    const float invN = 1.f / (float)N;
    size_t total = (size_t)N * OUT;
    for (size_t i = (size_t)blockIdx.x * blockDim.x + threadIdx.x; i < total;
         i += (size_t)gridDim.x * blockDim.x) {
        int c = (int)(i & (OUT - 1));
        float mean = g_sum[LAYER][c] * invN;
        float var  = g_sq[LAYER][c] * invN - mean * mean;
        float r = rsqrtf(var + 1e-5f);
        out[i] = (t[i] - mean) * r;
    }
}

// ---------------------------------------------------------------------------
extern "C" void kernel_launch(void* const* d_in, const int* in_sizes, int n_in,
                              void* d_out, int out_size) {
    const float* x        = (const float*)d_in[0];
    const int*   adj_row  = (const int*)d_in[1];
    const int*   adj_col  = (const int*)d_in[2];
    const float* adj_vals = (const float*)d_in[3];
    const float* W1 = (const float*)d_in[4];
    const float* W2 = (const float*)d_in[5];
    const float* W3 = (const float*)d_in[6];
    const float* W4 = (const float*)d_in[7];
    float* out = (float*)d_out;

    const int N = in_sizes[0] / 256;
    const int E = in_sizes[1];

    float* g_support_p; cudaGetSymbolAddress((void**)&g_support_p, g_support);
    float* g_t_p;       cudaGetSymbolAddress((void**)&g_t_p, g_t);

    float* h1 = out;                       // [N,128]
    float* h2 = out + (size_t)N * 128;     // [N,128]
    float* h3 = out + (size_t)N * 256;     // [N,64]
    float* h4 = out + (size_t)N * 320;     // [N,32]

    zero_stats_kernel<<<1, 128>>>();
    rowptr_kernel<<<(N + 256) / 256, 256>>>(adj_row, N, E);

    dim3 gthr(16, 16);
    const int gemm_blocks = (N + 63) / 64;
    const int spmm_blocks = (N + 7) / 8;
    const int norm_blocks = 1184;  // 8 * 148

    // Layer 1: x[N,256] @ W1[256,128]
    gemm_kernel<256, 128><<<gemm_blocks, gthr>>>(x, W1, g_support_p, N);
    spmm_kernel<128, 0><<<spmm_blocks, 256>>>(g_support_p, adj_col, adj_vals, g_t_p, N);
    norm_kernel<128, 0><<<norm_blocks, 256>>>(g_t_p, h1, N);

    // Layer 2: h1[N,128] @ W2[128,128]
    gemm_kernel<128, 128><<<gemm_blocks, gthr>>>(h1, W2, g_support_p, N);
    spmm_kernel<128, 1><<<spmm_blocks, 256>>>(g_support_p, adj_col, adj_vals, g_t_p, N);
    norm_kernel<128, 1><<<norm_blocks, 256>>>(g_t_p, h2, N);

    // Layer 3: h2[N,128] @ W3[128,64]
    gemm_kernel<128, 64><<<gemm_blocks, gthr>>>(h2, W3, g_support_p, N);
    spmm_kernel<64, 2><<<spmm_blocks, 256>>>(g_support_p, adj_col, adj_vals, g_t_p, N);
    norm_kernel<64, 2><<<norm_blocks, 256>>>(g_t_p, h3, N);

    // Layer 4: h3[N,64] @ W4[64,32]
    gemm_kernel<64, 32><<<gemm_blocks, gthr>>>(h3, W4, g_support_p, N);
    spmm_kernel<32, 3><<<spmm_blocks, 256>>>(g_support_p, adj_col, adj_vals, g_t_p, N);
    norm_kernel<32, 3><<<norm_blocks, 256>>>(g_t_p, h4, N);
}